// round 10
// baseline (speedup 1.0000x reference)
#include <cuda_runtime.h>

// Problem constants
#define Bc 2
#define Lc 2048
#define Ec 1024
#define Hc 16
#define Dc 64

// Scratch (device globals -- no allocations allowed)
__device__ float g_q[Bc*Hc*Lc*Dc];    // [B,H,L,D] projected Q
__device__ float g_k[Bc*Hc*Lc*Dc];    // [B,H,L,D] projected K
__device__ float g_v[Bc*Hc*Lc*Dc];    // [B,H,L,D] projected V
__device__ float g_ctx[Bc*Lc*Ec];     // [B,L,H,D] attention output (pre-FC)

// ---------------------------------------------------------------------------
// Per-head projection: out[b,h,l,e] = sum_d x[b,l,h*64+d] * W[e,d]
// One block per (b,l); 1024 threads: thread t -> (h = t/64, e = t%64).
// ---------------------------------------------------------------------------
__global__ __launch_bounds__(1024)
void proj_kernel(const float* __restrict__ x, const float* __restrict__ W, int which) {
    __shared__ __align__(16) float sW[64*68];   // W row-major, padded row stride 68
    __shared__ __align__(16) float sx[1024];
    int t  = threadIdx.x;
    int bl = blockIdx.x;

#pragma unroll
    for (int i = 0; i < 4; i++) {
        int idx = t + i*1024;              // 4096 elems of W
        int e = idx >> 6, d = idx & 63;
        sW[e*68 + d] = W[idx];
    }
    sx[t] = x[(size_t)bl*1024 + t];
    __syncthreads();

    int h = t >> 6, e = t & 63;
    const float* xh = sx + h*64;
    const float* wr = sW + e*68;
    float acc = 0.f;
#pragma unroll
    for (int d4 = 0; d4 < 16; d4++) {
        float4 xv = *reinterpret_cast<const float4*>(xh + d4*4);
        float4 wv = *reinterpret_cast<const float4*>(wr + d4*4);
        acc += xv.x*wv.x + xv.y*wv.y + xv.z*wv.z + xv.w*wv.w;
    }
    float* out = (which == 0) ? g_q : (which == 1) ? g_k : g_v;
    int b = bl >> 11, l = bl & 2047;    // bl = b*2048 + l
    out[(((size_t)(b*Hc + h))*Lc + l)*Dc + e] = acc;
}

// ---------------------------------------------------------------------------
// Fused flash attention, fp32. grid = (L/64, B*H), block = 256.
// Block tile: 64 q-rows x 64 k-cols per iteration, D = 64.
// Thread (tx = tid&15, ty = tid>>4):
//   S frag: rows ty*4+i, cols tx+16j   (4x4)
//   O frag: rows ty*4+i, cols tx*4+j   (4x4)
// K/V share one smem buffer with a rotation swizzle:
//   float4-slot c4 of row r stored at physical slot (c4 + r) & 15
// -> all smem traffic is conflict-free float4; total static smem = 48 KB.
// ---------------------------------------------------------------------------
__global__ __launch_bounds__(256)
void attn_kernel(const int* __restrict__ mask) {
    __shared__ __align__(16) float sQ [64*64];
    __shared__ __align__(16) float sKV[64*64];
    __shared__ __align__(16) float sP [64*64];

    int bh = blockIdx.y;
    int b  = bh >> 4;
    int h  = bh & 15;
    int q0 = blockIdx.x * 64;
    int tid = threadIdx.x;
    int tx = tid & 15, ty = tid >> 4;

    const float* Qb = g_q + (size_t)bh * Lc * Dc;
    const float* Kb = g_k + (size_t)bh * Lc * Dc;
    const float* Vb = g_v + (size_t)bh * Lc * Dc;
    const int* maskb = mask + (size_t)b * Lc * Lc;

    // Load Q tile [64][64] row-major (reads are ty-broadcast -> no pad needed)
    {
        const float4* src = reinterpret_cast<const float4*>(Qb + (size_t)q0 * 64);
        float4* dst = reinterpret_cast<float4*>(sQ);
#pragma unroll
        for (int i = 0; i < 4; i++) dst[tid + i*256] = src[tid + i*256];
    }

    float o[4][4];
    float m_i[4], l_i[4];
#pragma unroll
    for (int i = 0; i < 4; i++) {
        m_i[i] = -3.402823466e38f;
        l_i[i] = 0.f;
#pragma unroll
        for (int j = 0; j < 4; j++) o[i][j] = 0.f;
    }

    for (int k0 = 0; k0 < Lc; k0 += 64) {
        __syncthreads();   // previous stage-B reads of sKV/sP complete
        // Load K tile with rotation swizzle
#pragma unroll
        for (int i = 0; i < 4; i++) {
            int idx = tid + i*256;
            int r = idx >> 4, c4 = idx & 15;
            int ps = (c4 + r) & 15;
            *reinterpret_cast<float4*>(sKV + r*64 + ps*4) =
                *reinterpret_cast<const float4*>(Kb + (size_t)(k0 + r)*64 + c4*4);
        }
        __syncthreads();

        // ---- Stage A: S = Q * K^T ----
        float s[4][4];
#pragma unroll
        for (int i = 0; i < 4; i++)
#pragma unroll
            for (int j = 0; j < 4; j++) s[i][j] = 0.f;

#pragma unroll 4
        for (int d4 = 0; d4 < 16; d4++) {
            float a[4][4], kk[4][4];
#pragma unroll
            for (int i = 0; i < 4; i++) {
                float4 t4 = *reinterpret_cast<const float4*>(sQ + (ty*4 + i)*64 + d4*4);
                a[i][0] = t4.x; a[i][1] = t4.y; a[i][2] = t4.z; a[i][3] = t4.w;
            }
#pragma unroll
            for (int j = 0; j < 4; j++) {
                int n = tx + 16*j;
                float4 t4 = *reinterpret_cast<const float4*>(sKV + n*64 + (((d4 + n) & 15) << 2));
                kk[j][0] = t4.x; kk[j][1] = t4.y; kk[j][2] = t4.z; kk[j][3] = t4.w;
            }
#pragma unroll
            for (int i = 0; i < 4; i++)
#pragma unroll
                for (int j = 0; j < 4; j++)
#pragma unroll
                    for (int d = 0; d < 4; d++)
                        s[i][j] += a[i][d] * kk[j][d];
        }

        // ---- mask (before scale, as in reference), scale by 1/sqrt(E)=1/32,
        //      online softmax update ----
#pragma unroll
        for (int i = 0; i < 4; i++) {
            const int* mrow = maskb + (size_t)(q0 + ty*4 + i) * Lc + k0;
            float rmax = -3.402823466e38f;
#pragma unroll
            for (int j = 0; j < 4; j++) {
                float sv = s[i][j];
                if (mrow[tx + 16*j] == 0) sv = -1e20f;
                sv *= 0.03125f;
                s[i][j] = sv;
                rmax = fmaxf(rmax, sv);
            }
#pragma unroll
            for (int w = 1; w < 16; w <<= 1)
                rmax = fmaxf(rmax, __shfl_xor_sync(0xffffffffu, rmax, w));
            float mn = fmaxf(m_i[i], rmax);
            float scale = __expf(m_i[i] - mn);
            m_i[i] = mn;
            float rsum = 0.f;
#pragma unroll
            for (int j = 0; j < 4; j++) {
                float p = __expf(s[i][j] - mn);
                s[i][j] = p;
                rsum += p;
            }
#pragma unroll
            for (int w = 1; w < 16; w <<= 1)
                rsum += __shfl_xor_sync(0xffffffffu, rsum, w);
            l_i[i] = l_i[i] * scale + rsum;
#pragma unroll
            for (int j = 0; j < 4; j++) o[i][j] *= scale;
        }

        __syncthreads();   // all threads done reading sKV as K
        // Load V tile into the same buffer; write P to sP
#pragma unroll
        for (int i = 0; i < 4; i++) {
            int idx = tid + i*256;
            int r = idx >> 4, c4 = idx & 15;
            int ps = (c4 + r) & 15;
            *reinterpret_cast<float4*>(sKV + r*64 + ps*4) =
                *reinterpret_cast<const float4*>(Vb + (size_t)(k0 + r)*64 + c4*4);
        }
#pragma unroll
        for (int i = 0; i < 4; i++)
#pragma unroll
            for (int j = 0; j < 4; j++)
                sP[(ty*4 + i)*64 + tx + 16*j] = s[i][j];
        __syncthreads();

        // ---- Stage B: O += P * V ----
#pragma unroll 4
        for (int n4 = 0; n4 < 16; n4++) {
            float pp[4][4], vv[4][4];
#pragma unroll
            for (int i = 0; i < 4; i++) {
                float4 t4 = *reinterpret_cast<const float4*>(sP + (ty*4 + i)*64 + n4*4);
                pp[i][0] = t4.x; pp[i][1] = t4.y; pp[i][2] = t4.z; pp[i][3] = t4.w;
            }
#pragma unroll
            for (int nn = 0; nn < 4; nn++) {
                int n = n4*4 + nn;
                float4 t4 = *reinterpret_cast<const float4*>(sKV + n*64 + (((tx + n) & 15) << 2));
                vv[nn][0] = t4.x; vv[nn][1] = t4.y; vv[nn][2] = t4.z; vv[nn][3] = t4.w;
            }
#pragma unroll
            for (int i = 0; i < 4; i++)
#pragma unroll
                for (int j = 0; j < 4; j++)
#pragma unroll
                    for (int nn = 0; nn < 4; nn++)
                        o[i][j] += pp[i][nn] * vv[nn][j];
        }
    }

    // Epilogue: normalize, write ctx[b, q, h, d]
#pragma unroll
    for (int i = 0; i < 4; i++) {
        float inv = 1.f / l_i[i];
        int q = q0 + ty*4 + i;
        float4 r;
        r.x = o[i][0]*inv; r.y = o[i][1]*inv; r.z = o[i][2]*inv; r.w = o[i][3]*inv;
        *reinterpret_cast<float4*>(g_ctx + ((size_t)(b*Lc + q)*Hc + h)*Dc + tx*4) = r;
    }
}

// ---------------------------------------------------------------------------
// FC: out[n,f] = sum_e ctx[n,e] * Wfc[f,e] + bfc[f]
// Same 64x64 tiling / 4x4 frags; Wfc tile uses the rotation swizzle.
// grid = (E/64, (B*L)/64), block = 256.
// ---------------------------------------------------------------------------
__global__ __launch_bounds__(256)
void fc_kernel(const float* __restrict__ W, const float* __restrict__ bias,
               float* __restrict__ out) {
    __shared__ __align__(16) float sA[64*64];
    __shared__ __align__(16) float sB[64*64];
    int tid = threadIdx.x;
    int tx = tid & 15, ty = tid >> 4;
    int f0 = blockIdx.x * 64;
    int n0 = blockIdx.y * 64;

    float acc[4][4];
#pragma unroll
    for (int i = 0; i < 4; i++)
#pragma unroll
        for (int j = 0; j < 4; j++) acc[i][j] = 0.f;

    for (int kc = 0; kc < Ec; kc += 64) {
        __syncthreads();
#pragma unroll
        for (int i = 0; i < 4; i++) {
            int idx = tid + i*256;
            int r = idx >> 4, c4 = idx & 15;
            *reinterpret_cast<float4*>(sA + r*64 + c4*4) =
                *reinterpret_cast<const float4*>(g_ctx + (size_t)(n0 + r)*Ec + kc + c4*4);
            *reinterpret_cast<float4*>(sB + r*64 + (((c4 + r) & 15) << 2)) =
                *reinterpret_cast<const float4*>(W + (size_t)(f0 + r)*Ec + kc + c4*4);
        }
        __syncthreads();

#pragma unroll 4
        for (int d4 = 0; d4 < 16; d4++) {
            float a[4][4], bb[4][4];
#pragma unroll
            for (int i = 0; i < 4; i++) {
                float4 t4 = *reinterpret_cast<const float4*>(sA + (ty*4 + i)*64 + d4*4);
                a[i][0] = t4.x; a[i][1] = t4.y; a[i][2] = t4.z; a[i][3] = t4.w;
            }
#pragma unroll
            for (int j = 0; j < 4; j++) {
                int n = tx + 16*j;
                float4 t4 = *reinterpret_cast<const float4*>(sB + n*64 + (((d4 + n) & 15) << 2));
                bb[j][0] = t4.x; bb[j][1] = t4.y; bb[j][2] = t4.z; bb[j][3] = t4.w;
            }
#pragma unroll
            for (int i = 0; i < 4; i++)
#pragma unroll
                for (int j = 0; j < 4; j++)
#pragma unroll
                    for (int d = 0; d < 4; d++)
                        acc[i][j] += a[i][d] * bb[j][d];
        }
    }

#pragma unroll
    for (int j = 0; j < 4; j++) {
        int f = f0 + tx + 16*j;
        float bv = bias[f];
#pragma unroll
        for (int i = 0; i < 4; i++)
            out[(size_t)(n0 + ty*4 + i)*Ec + f] = acc[i][j] + bv;
    }
}

// ---------------------------------------------------------------------------
// Launch. Input order (metadata): query, value, key, mask, Wq, Wk, Wv, Wfc, bfc
// ---------------------------------------------------------------------------
extern "C" void kernel_launch(void* const* d_in, const int* in_sizes, int n_in,
                              void* d_out, int out_size) {
    (void)in_sizes; (void)n_in; (void)out_size;
    const float* query = (const float*)d_in[0];
    const float* value = (const float*)d_in[1];   // NOTE: value is d_in[1]
    const float* keyt  = (const float*)d_in[2];   // NOTE: key   is d_in[2]
    const int*   mask  = (const int*)  d_in[3];
    const float* Wq    = (const float*)d_in[4];
    const float* Wk    = (const float*)d_in[5];
    const float* Wv    = (const float*)d_in[6];
    const float* Wfc   = (const float*)d_in[7];
    const float* bfc   = (const float*)d_in[8];
    float* out = (float*)d_out;

    proj_kernel<<<Bc*Lc, 1024>>>(query, Wq, 0);
    proj_kernel<<<Bc*Lc, 1024>>>(keyt,  Wk, 1);
    proj_kernel<<<Bc*Lc, 1024>>>(value, Wv, 2);

    attn_kernel<<<dim3(Lc/64, Bc*Hc), 256>>>(mask);

    fc_kernel<<<dim3(Ec/64, (Bc*Lc)/64), 256>>>(Wfc, bfc, out);
}

// round 11
// speedup vs baseline: 1.7074x; 1.7074x over previous
#include <cuda_runtime.h>
#include <cstdint>

// Problem constants
#define Bc 2
#define Lc 2048
#define Ec 1024
#define Hc 16
#define Dc 64

// Scratch (device globals -- no allocations allowed)
__device__ float g_q[Bc*Hc*Lc*Dc];       // [B,H,L,D] projected Q
__device__ float g_k[Bc*Hc*Lc*Dc];       // [B,H,L,D] projected K
__device__ float g_v[Bc*Hc*Lc*Dc];       // [B,H,L,D] projected V
__device__ float g_ctx[Bc*Lc*Ec];        // [B,L,H,D] attention output (pre-FC)
__device__ unsigned g_mb[Bc*Lc*Lc/32];   // packed mask bits

// ---------------------------------------------------------------------------
// helpers
// ---------------------------------------------------------------------------
__device__ __forceinline__ unsigned f2tf32(float x) {
    unsigned r; asm("cvt.rna.tf32.f32 %0, %1;" : "=r"(r) : "f"(x)); return r;
}
__device__ __forceinline__ float ex2(float x) {
    float r; asm("ex2.approx.f32 %0, %1;" : "=f"(r) : "f"(x)); return r;
}
__device__ __forceinline__ void mma_tf32(float c[4], const unsigned a[4], const unsigned b0, const unsigned b1) {
    asm volatile(
        "mma.sync.aligned.m16n8k8.row.col.f32.tf32.tf32.f32 "
        "{%0,%1,%2,%3}, {%4,%5,%6,%7}, {%8,%9}, {%0,%1,%2,%3};"
        : "+f"(c[0]), "+f"(c[1]), "+f"(c[2]), "+f"(c[3])
        : "r"(a[0]), "r"(a[1]), "r"(a[2]), "r"(a[3]), "r"(b0), "r"(b1));
}

// ---------------------------------------------------------------------------
// mask -> bitmask pack: one bit per mask element (1 = keep)
// ---------------------------------------------------------------------------
__global__ __launch_bounds__(256)
void mask_pack_kernel(const int* __restrict__ mask) {
    int i = blockIdx.x * 256 + threadIdx.x;
    int v = mask[i];
    unsigned bal = __ballot_sync(0xffffffffu, v != 0);
    if ((threadIdx.x & 31) == 0) g_mb[i >> 5] = bal;
}

// ---------------------------------------------------------------------------
// Per-head projection: out[b,h,l,e] = sum_d x[b,l,h*64+d] * W[e,d]
// ---------------------------------------------------------------------------
__global__ __launch_bounds__(1024)
void proj_kernel(const float* __restrict__ x, const float* __restrict__ W, int which) {
    __shared__ __align__(16) float sW[64*68];
    __shared__ __align__(16) float sx[1024];
    int t  = threadIdx.x;
    int bl = blockIdx.x;

#pragma unroll
    for (int i = 0; i < 4; i++) {
        int idx = t + i*1024;
        int e = idx >> 6, d = idx & 63;
        sW[e*68 + d] = W[idx];
    }
    sx[t] = x[(size_t)bl*1024 + t];
    __syncthreads();

    int h = t >> 6, e = t & 63;
    const float* xh = sx + h*64;
    const float* wr = sW + e*68;
    float acc = 0.f;
#pragma unroll
    for (int d4 = 0; d4 < 16; d4++) {
        float4 xv = *reinterpret_cast<const float4*>(xh + d4*4);
        float4 wv = *reinterpret_cast<const float4*>(wr + d4*4);
        acc += xv.x*wv.x + xv.y*wv.y + xv.z*wv.z + xv.w*wv.w;
    }
    float* out = (which == 0) ? g_q : (which == 1) ? g_k : g_v;
    int b = bl >> 11, l = bl & 2047;
    out[(((size_t)(b*Hc + h))*Lc + l)*Dc + e] = acc;
}

// ---------------------------------------------------------------------------
// Tensor-core flash attention (tf32 mma.sync, fp32 accum).
// grid = (L/128, B*H), block = 256 (8 warps). Warp w owns 16 q-rows.
// S (16x64) lives in C-fragments; softmax is warp-local; P converted to
// A-fragments in-register via quad shuffles. smem stride 72 = conflict-free.
// ---------------------------------------------------------------------------
#define QT 128
#define SSTR 72
#define SCALE_LOG2E 0.04508422f   /* (1/32) * log2(e) */

#define LD_KV(base, kk0) do { \
    _Pragma("unroll") \
    for (int i_ = 0; i_ < 4; i_++) { \
        int j_ = tid + i_*256; \
        kvreg[i_] = *reinterpret_cast<const float4*>((base) + (size_t)((kk0) + (j_>>4))*64 + (j_&15)*4); \
    } } while(0)

#define ST_KV() do { \
    _Pragma("unroll") \
    for (int i_ = 0; i_ < 4; i_++) { \
        int j_ = tid + i_*256; \
        uint4 t_; \
        t_.x = f2tf32(kvreg[i_].x); t_.y = f2tf32(kvreg[i_].y); \
        t_.z = f2tf32(kvreg[i_].z); t_.w = f2tf32(kvreg[i_].w); \
        *reinterpret_cast<uint4*>(sm + (j_>>4)*SSTR + (j_&15)*4) = t_; \
    } } while(0)

__global__ __launch_bounds__(256)
void attn_tc_kernel() {
    __shared__ __align__(16) unsigned sm[QT * SSTR];   // Q staging, then K/V tiles

    int tid  = threadIdx.x;
    int w    = tid >> 5;
    int lane = tid & 31;
    int gy   = lane >> 2;   // 0..7
    int gx   = lane & 3;    // 0..3

    int bh = blockIdx.y;
    int bi = bh >> 4;
    int h  = bh & 15;
    int q0 = blockIdx.x * QT;

    const float* Qb = g_q + (size_t)bh * Lc * Dc;
    const float* Kb = g_k + (size_t)bh * Lc * Dc;
    const float* Vb = g_v + (size_t)bh * Lc * Dc;

    // ---- stage Q tile [128][64] into smem (tf32-rounded), then into regs ----
#pragma unroll
    for (int i = 0; i < 8; i++) {
        int j = tid + i*256;                  // float4 slot: row = j>>4, c4 = j&15
        float4 v = *reinterpret_cast<const float4*>(Qb + (size_t)(q0 + (j>>4))*64 + (j&15)*4);
        uint4 t;
        t.x = f2tf32(v.x); t.y = f2tf32(v.y); t.z = f2tf32(v.z); t.w = f2tf32(v.w);
        *reinterpret_cast<uint4*>(sm + (j>>4)*SSTR + (j&15)*4) = t;
    }
    __syncthreads();

    unsigned qa[8][4];
    int row0 = w*16 + gy;
#pragma unroll
    for (int kt = 0; kt < 8; kt++) {
        qa[kt][0] = sm[ row0     *SSTR + kt*8 + gx    ];
        qa[kt][1] = sm[(row0 + 8)*SSTR + kt*8 + gx    ];
        qa[kt][2] = sm[ row0     *SSTR + kt*8 + gx + 4];
        qa[kt][3] = sm[(row0 + 8)*SSTR + kt*8 + gx + 4];
    }

    float oc[8][4];
    float m2[2], l2[2];
#pragma unroll
    for (int i = 0; i < 8; i++)
#pragma unroll
        for (int j = 0; j < 4; j++) oc[i][j] = 0.f;
    m2[0] = m2[1] = -3.402823466e38f;
    l2[0] = l2[1] = 0.f;

    int qrow0 = q0 + w*16 + gy;
    const unsigned* mb_row0 = g_mb + (size_t)(bi*Lc + qrow0    ) * 64;
    const unsigned* mb_row1 = g_mb + (size_t)(bi*Lc + qrow0 + 8) * 64;

    float4 kvreg[4];
    LD_KV(Kb, 0);   // prefetch first K tile

    for (int k0 = 0; k0 < Lc; k0 += 64) {
        __syncthreads();                 // (1) prior V reads done
        ST_KV();                         // K tile -> smem
        __syncthreads();                 // (2)

        // ---- stage A: S = Q K^T (16x64 per warp) ----
        float sc[8][4];
#pragma unroll
        for (int i = 0; i < 8; i++)
#pragma unroll
            for (int j = 0; j < 4; j++) sc[i][j] = 0.f;

#pragma unroll
        for (int kt = 0; kt < 8; kt++) {
#pragma unroll
            for (int nt = 0; nt < 8; nt++) {
                unsigned b0 = sm[(nt*8 + gy)*SSTR + kt*8 + gx    ];
                unsigned b1 = sm[(nt*8 + gy)*SSTR + kt*8 + gx + 4];
                mma_tf32(sc[nt], qa[kt], b0, b1);
            }
        }
        __syncthreads();                 // (3) done reading K

        LD_KV(Vb, k0);                   // prefetch V under softmax

        // ---- mask (before scale), scale via log2-domain, online softmax ----
        int wsel = k0 >> 5;
#pragma unroll
        for (int i = 0; i < 2; i++) {
            const unsigned* mrow = (i == 0) ? mb_row0 : mb_row1;
            unsigned mw0 = mrow[wsel], mw1 = mrow[wsel + 1];
            float rmax = -3.402823466e38f;
#pragma unroll
            for (int nt = 0; nt < 8; nt++) {
                unsigned mw = (nt < 4) ? mw0 : mw1;
                int c = (nt*8 + 2*gx) & 31;
                float t0 = ((mw >> c)     & 1u) ? sc[nt][2*i  ] * SCALE_LOG2E : -4.5e18f;
                float t1 = ((mw >> (c+1)) & 1u) ? sc[nt][2*i+1] * SCALE_LOG2E : -4.5e18f;
                sc[nt][2*i] = t0; sc[nt][2*i+1] = t1;
                rmax = fmaxf(rmax, fmaxf(t0, t1));
            }
            rmax = fmaxf(rmax, __shfl_xor_sync(0xffffffffu, rmax, 1));
            rmax = fmaxf(rmax, __shfl_xor_sync(0xffffffffu, rmax, 2));
            float mn = fmaxf(m2[i], rmax);
            float corr = ex2(m2[i] - mn);
            m2[i] = mn;
            float rsum = 0.f;
#pragma unroll
            for (int nt = 0; nt < 8; nt++) {
                float p0 = ex2(sc[nt][2*i]   - mn);
                float p1 = ex2(sc[nt][2*i+1] - mn);
                sc[nt][2*i] = p0; sc[nt][2*i+1] = p1;
                rsum += p0 + p1;
                oc[nt][2*i]   *= corr;
                oc[nt][2*i+1] *= corr;
            }
            rsum += __shfl_xor_sync(0xffffffffu, rsum, 1);
            rsum += __shfl_xor_sync(0xffffffffu, rsum, 2);
            l2[i] = l2[i]*corr + rsum;
        }

        // ---- convert P: C-fragment layout -> A-fragment layout (quad shfl) ----
        unsigned pa[8][4];
        int srcA = (lane & ~3) + (gx >> 1);
        bool odd = (gx & 1);
#pragma unroll
        for (int nt = 0; nt < 8; nt++) {
            float A0 = __shfl_sync(0xffffffffu, sc[nt][0], srcA);
            float A1 = __shfl_sync(0xffffffffu, sc[nt][1], srcA);
            float A2 = __shfl_sync(0xffffffffu, sc[nt][2], srcA);
            float A3 = __shfl_sync(0xffffffffu, sc[nt][3], srcA);
            float B0 = __shfl_sync(0xffffffffu, sc[nt][0], srcA + 2);
            float B1 = __shfl_sync(0xffffffffu, sc[nt][1], srcA + 2);
            float B2 = __shfl_sync(0xffffffffu, sc[nt][2], srcA + 2);
            float B3 = __shfl_sync(0xffffffffu, sc[nt][3], srcA + 2);
            pa[nt][0] = f2tf32(odd ? A1 : A0);
            pa[nt][1] = f2tf32(odd ? A3 : A2);
            pa[nt][2] = f2tf32(odd ? B1 : B0);
            pa[nt][3] = f2tf32(odd ? B3 : B2);
        }

        ST_KV();                         // V tile -> smem
        __syncthreads();                 // (4)

        if (k0 + 64 < Lc) LD_KV(Kb, k0 + 64);   // prefetch next K under stage B

        // ---- stage B: O += P V ----
#pragma unroll
        for (int kt = 0; kt < 8; kt++) {
#pragma unroll
            for (int nt = 0; nt < 8; nt++) {
                unsigned b0 = sm[(kt*8 + gx    )*SSTR + nt*8 + gy];
                unsigned b1 = sm[(kt*8 + gx + 4)*SSTR + nt*8 + gy];
                mma_tf32(oc[nt], pa[kt], b0, b1);
            }
        }
    }

    // ---- epilogue: normalize, write ctx[b, q, h, d] ----
    float inv0 = 1.f / l2[0];
    float inv1 = 1.f / l2[1];
    float* outa = g_ctx + ((size_t)(bi*Lc + qrow0    )*Hc + h)*Dc;
    float* outb = g_ctx + ((size_t)(bi*Lc + qrow0 + 8)*Hc + h)*Dc;
#pragma unroll
    for (int nt = 0; nt < 8; nt++) {
        int d = nt*8 + 2*gx;
        *reinterpret_cast<float2*>(outa + d) = make_float2(oc[nt][0]*inv0, oc[nt][1]*inv0);
        *reinterpret_cast<float2*>(outb + d) = make_float2(oc[nt][2]*inv1, oc[nt][3]*inv1);
    }
}

// ---------------------------------------------------------------------------
// FC (tf32 mma): out[n,f] = sum_e ctx[n,e]*Wfc[f,e] + bfc[f]
// grid = (E/64, (B*L)/128), block 256. 128(m) x 64(n) tile, k-chunk 32.
// ---------------------------------------------------------------------------
#define FSTR 40

__global__ __launch_bounds__(256)
void fc_tc_kernel(const float* __restrict__ W, const float* __restrict__ bias,
                  float* __restrict__ out) {
    __shared__ __align__(16) unsigned sA[128*FSTR];
    __shared__ __align__(16) unsigned sB[64*FSTR];

    int tid  = threadIdx.x;
    int w    = tid >> 5;
    int lane = tid & 31;
    int gy   = lane >> 2;
    int gx   = lane & 3;
    int f0 = blockIdx.x * 64;
    int n0 = blockIdx.y * 128;

    float oc[8][4];
#pragma unroll
    for (int i = 0; i < 8; i++)
#pragma unroll
        for (int j = 0; j < 4; j++) oc[i][j] = 0.f;

    float4 ar[4], br[2];
    // prefetch chunk 0
#pragma unroll
    for (int i = 0; i < 4; i++) {
        int j = tid + i*256;   // row = j>>3, c4 = j&7  (128 x 32 tile)
        ar[i] = *reinterpret_cast<const float4*>(g_ctx + (size_t)(n0 + (j>>3))*Ec + (j&7)*4);
    }
#pragma unroll
    for (int i = 0; i < 2; i++) {
        int j = tid + i*256;   // 64 x 32 tile
        br[i] = *reinterpret_cast<const float4*>(W + (size_t)(f0 + (j>>3))*Ec + (j&7)*4);
    }

    int row0 = w*16 + gy;
    for (int kc = 0; kc < Ec; kc += 32) {
        __syncthreads();
#pragma unroll
        for (int i = 0; i < 4; i++) {
            int j = tid + i*256;
            uint4 t;
            t.x = f2tf32(ar[i].x); t.y = f2tf32(ar[i].y);
            t.z = f2tf32(ar[i].z); t.w = f2tf32(ar[i].w);
            *reinterpret_cast<uint4*>(sA + (j>>3)*FSTR + (j&7)*4) = t;
        }
#pragma unroll
        for (int i = 0; i < 2; i++) {
            int j = tid + i*256;
            uint4 t;
            t.x = f2tf32(br[i].x); t.y = f2tf32(br[i].y);
            t.z = f2tf32(br[i].z); t.w = f2tf32(br[i].w);
            *reinterpret_cast<uint4*>(sB + (j>>3)*FSTR + (j&7)*4) = t;
        }
        __syncthreads();

        if (kc + 32 < Ec) {
#pragma unroll
            for (int i = 0; i < 4; i++) {
                int j = tid + i*256;
                ar[i] = *reinterpret_cast<const float4*>(g_ctx + (size_t)(n0 + (j>>3))*Ec + kc + 32 + (j&7)*4);
            }
#pragma unroll
            for (int i = 0; i < 2; i++) {
                int j = tid + i*256;
                br[i] = *reinterpret_cast<const float4*>(W + (size_t)(f0 + (j>>3))*Ec + kc + 32 + (j&7)*4);
            }
        }

        unsigned aa[4][4];
#pragma unroll
        for (int kt = 0; kt < 4; kt++) {
            aa[kt][0] = sA[ row0     *FSTR + kt*8 + gx    ];
            aa[kt][1] = sA[(row0 + 8)*FSTR + kt*8 + gx    ];
            aa[kt][2] = sA[ row0     *FSTR + kt*8 + gx + 4];
            aa[kt][3] = sA[(row0 + 8)*FSTR + kt*8 + gx + 4];
        }
#pragma unroll
        for (int kt = 0; kt < 4; kt++) {
#pragma unroll
            for (int nt = 0; nt < 8; nt++) {
                unsigned b0 = sB[(nt*8 + gy)*FSTR + kt*8 + gx    ];
                unsigned b1 = sB[(nt*8 + gy)*FSTR + kt*8 + gx + 4];
                mma_tf32(oc[nt], aa[kt], b0, b1);
            }
        }
    }

    // epilogue with bias
#pragma unroll
    for (int nt = 0; nt < 8; nt++) {
        int f = f0 + nt*8 + 2*gx;
        float2 bv = *reinterpret_cast<const float2*>(bias + f);
        *reinterpret_cast<float2*>(out + (size_t)(n0 + row0    )*Ec + f) =
            make_float2(oc[nt][0] + bv.x, oc[nt][1] + bv.y);
        *reinterpret_cast<float2*>(out + (size_t)(n0 + row0 + 8)*Ec + f) =
            make_float2(oc[nt][2] + bv.x, oc[nt][3] + bv.y);
    }
}

// ---------------------------------------------------------------------------
// Launch. Input order: query, value, key, mask, Wq, Wk, Wv, Wfc, bfc
// ---------------------------------------------------------------------------
extern "C" void kernel_launch(void* const* d_in, const int* in_sizes, int n_in,
                              void* d_out, int out_size) {
    (void)in_sizes; (void)n_in; (void)out_size;
    const float* query = (const float*)d_in[0];
    const float* value = (const float*)d_in[1];
    const float* keyt  = (const float*)d_in[2];
    const int*   mask  = (const int*)  d_in[3];
    const float* Wq    = (const float*)d_in[4];
    const float* Wk    = (const float*)d_in[5];
    const float* Wv    = (const float*)d_in[6];
    const float* Wfc   = (const float*)d_in[7];
    const float* bfc   = (const float*)d_in[8];
    float* out = (float*)d_out;

    proj_kernel<<<Bc*Lc, 1024>>>(query, Wq, 0);
    proj_kernel<<<Bc*Lc, 1024>>>(keyt,  Wk, 1);
    proj_kernel<<<Bc*Lc, 1024>>>(value, Wv, 2);
    mask_pack_kernel<<<(Bc*Lc*Lc)/256, 256>>>(mask);

    attn_tc_kernel<<<dim3(Lc/QT, Bc*Hc), 256>>>();

    fc_tc_kernel<<<dim3(Ec/64, (Bc*Lc)/128), 256>>>(Wfc, bfc, out);
}